// round 1
// baseline (speedup 1.0000x reference)
#include <cuda_runtime.h>
#include <math.h>

#define Bc 4
#define Sc 2048
#define Ec 1024
#define Hc 16
#define Mc 256
#define Dc 64

// ---------------- scratch (device globals; no runtime allocation) ----------------
__device__ float g_Q[Bc*Sc*Ec];
__device__ float g_K[Bc*Sc*Ec];
__device__ float g_V[Bc*Sc*Ec];
__device__ float g_qp[(size_t)Bc*Hc*Sc*Mc];
__device__ float g_kp[(size_t)Bc*Hc*Sc*Mc];
__device__ float g_attn[Bc*Sc*Ec];
__device__ float g_res[Bc*Sc*Ec];

// ---------------- fp32 tiled GEMM: C = A@B + bias (+ add), row-major ----------------
// A: [Mr,K], B: [K,N], bias: [N], add: [Mr,N] or null, C: [Mr,N]
// BM=BN=128, BK=16, 256 threads, 8x8 per thread.
__global__ void __launch_bounds__(256)
sgemm_bias(const float* __restrict__ A, const float* __restrict__ B,
           const float* __restrict__ bias, const float* __restrict__ add,
           float* __restrict__ C, int Mr, int N, int K)
{
    __shared__ float As[16][128];
    __shared__ float Bs[16][128];
    const int tid  = threadIdx.x;
    const int tx   = tid & 15;
    const int ty   = tid >> 4;
    const int row0 = blockIdx.y * 128;
    const int col0 = blockIdx.x * 128;

    float acc[8][8];
    #pragma unroll
    for (int i = 0; i < 8; i++)
        #pragma unroll
        for (int j = 0; j < 8; j++) acc[i][j] = 0.f;

    for (int k0 = 0; k0 < K; k0 += 16) {
        #pragma unroll
        for (int i = 0; i < 2; i++) {
            int id = (tid << 1) + i;
            int r  = id >> 2;
            int kc = (id & 3) << 2;
            const float4 a = *(const float4*)(A + (size_t)(row0 + r) * K + k0 + kc);
            As[kc + 0][r] = a.x;
            As[kc + 1][r] = a.y;
            As[kc + 2][r] = a.z;
            As[kc + 3][r] = a.w;
            int kr = id >> 5;
            int nc = (id & 31) << 2;
            *(float4*)(&Bs[kr][nc]) = *(const float4*)(B + (size_t)(k0 + kr) * N + col0 + nc);
        }
        __syncthreads();
        #pragma unroll
        for (int k = 0; k < 16; k++) {
            float ra[8], rb[8];
            #pragma unroll
            for (int j = 0; j < 8; j++) ra[j] = As[k][ty * 8 + j];
            #pragma unroll
            for (int j = 0; j < 8; j++) rb[j] = Bs[k][tx * 8 + j];
            #pragma unroll
            for (int i = 0; i < 8; i++)
                #pragma unroll
                for (int j = 0; j < 8; j++)
                    acc[i][j] = fmaf(ra[i], rb[j], acc[i][j]);
        }
        __syncthreads();
    }

    #pragma unroll
    for (int i = 0; i < 8; i++) {
        const size_t rbase = (size_t)(row0 + ty * 8 + i) * N;
        #pragma unroll
        for (int j = 0; j < 8; j += 4) {
            const int ci = col0 + tx * 8 + j;
            float4 r;
            r.x = acc[i][j + 0] + bias[ci + 0];
            r.y = acc[i][j + 1] + bias[ci + 1];
            r.z = acc[i][j + 2] + bias[ci + 2];
            r.w = acc[i][j + 3] + bias[ci + 3];
            if (add) {
                const float4 av = *(const float4*)(add + rbase + ci);
                r.x += av.x; r.y += av.y; r.z += av.z; r.w += av.w;
            }
            *(float4*)(C + rbase + ci) = r;
        }
    }
}

// ---------------- feature map: qp[b,h,s,m] = (1/16) exp(dot(Q,proj_m)/8 - |Q|^2/128) ----------------
// A: QKV-style [ (b,s,h), d ] rows (length 64, contiguous). proj: [M, D].
// Tile: 128 rows x 128 m-cols per CTA, K = 64.
__global__ void __launch_bounds__(256)
feature_kernel(const float* __restrict__ A, const float* __restrict__ proj,
               float* __restrict__ out)
{
    __shared__ float As[16][128];
    __shared__ float Bs[16][128];
    __shared__ float s2[128][2];
    const int tid  = threadIdx.x;
    const int tx   = tid & 15;
    const int ty   = tid >> 4;
    const int row0 = blockIdx.y * 128;   // flattened (b,s,h)
    const int col0 = blockIdx.x * 128;   // m

    // per-row sum of squares (two threads per row, 32 elems each)
    {
        int r = tid >> 1, half = tid & 1;
        const float* p = A + (size_t)(row0 + r) * Dc + half * 32;
        float s = 0.f;
        #pragma unroll
        for (int i = 0; i < 32; i++) s = fmaf(p[i], p[i], s);
        s2[r][half] = s;
    }

    float acc[8][8];
    #pragma unroll
    for (int i = 0; i < 8; i++)
        #pragma unroll
        for (int j = 0; j < 8; j++) acc[i][j] = 0.f;

    for (int k0 = 0; k0 < Dc; k0 += 16) {
        #pragma unroll
        for (int i = 0; i < 2; i++) {
            int id = (tid << 1) + i;
            int r  = id >> 2;
            int kc = (id & 3) << 2;
            const float4 a = *(const float4*)(A + (size_t)(row0 + r) * Dc + k0 + kc);
            As[kc + 0][r] = a.x;
            As[kc + 1][r] = a.y;
            As[kc + 2][r] = a.z;
            As[kc + 3][r] = a.w;
            int kr = id >> 5;
            int nc = (id & 31) << 2;
            Bs[kr][nc + 0] = proj[(size_t)(col0 + nc + 0) * Dc + k0 + kr];
            Bs[kr][nc + 1] = proj[(size_t)(col0 + nc + 1) * Dc + k0 + kr];
            Bs[kr][nc + 2] = proj[(size_t)(col0 + nc + 2) * Dc + k0 + kr];
            Bs[kr][nc + 3] = proj[(size_t)(col0 + nc + 3) * Dc + k0 + kr];
        }
        __syncthreads();
        #pragma unroll
        for (int k = 0; k < 16; k++) {
            float ra[8], rb[8];
            #pragma unroll
            for (int j = 0; j < 8; j++) ra[j] = As[k][ty * 8 + j];
            #pragma unroll
            for (int j = 0; j < 8; j++) rb[j] = Bs[k][tx * 8 + j];
            #pragma unroll
            for (int i = 0; i < 8; i++)
                #pragma unroll
                for (int j = 0; j < 8; j++)
                    acc[i][j] = fmaf(ra[i], rb[j], acc[i][j]);
        }
        __syncthreads();
    }

    // epilogue: scale, exp, scatter to [b,h,s,m]
    #pragma unroll
    for (int i = 0; i < 8; i++) {
        const int rr = ty * 8 + i;
        const int r  = row0 + rr;
        const float ss = s2[rr][0] + s2[rr][1];
        const int b = r >> 15;            // S*H = 32768
        const int s = (r >> 4) & (Sc - 1);
        const int h = r & (Hc - 1);
        const size_t obase = ((size_t)(b * Hc + h) * Sc + s) * Mc + col0 + tx * 8;
        const float corr = ss * (1.f / 128.f);
        #pragma unroll
        for (int j = 0; j < 8; j++)
            out[obase + j] = 0.0625f * expf(fmaf(acc[i][j], 0.125f, -corr));
    }
}

// ---------------- causal linear-attention scan ----------------
// One CTA per (b,h). State kv[M][D] in registers: thread (c,d) owns kv[c*64..c*64+63][d].
// ksum[M] in shared (thread-private slots). Per step: ksum+=k; kv+=k*v; num=kv.q; den=q.ksum.
__global__ void __launch_bounds__(256)
scan_kernel(const float* __restrict__ qp, const float* __restrict__ kp,
            const float* __restrict__ V, float* __restrict__ attn)
{
    const int bh  = blockIdx.x;
    const int b   = bh >> 4;
    const int h   = bh & 15;
    const int tid = threadIdx.x;
    const int c   = tid >> 6;
    const int d   = tid & 63;

    __shared__ float q_sh[256], k_sh[256], v_sh[64];
    __shared__ float ksum_sh[256];
    __shared__ float nred[4][64];
    __shared__ float dred[8];

    float kv[64];
    #pragma unroll
    for (int i = 0; i < 64; i++) kv[i] = 0.f;
    ksum_sh[tid] = 0.f;

    const float* qpb = qp + (size_t)bh * Sc * Mc;
    const float* kpb = kp + (size_t)bh * Sc * Mc;
    const float* Vb  = V + ((size_t)b * Sc * Hc + h) * Dc;     // + s*Hc*Dc + d
    float*       ab  = attn + ((size_t)b * Sc * Hc + h) * Dc;  // + s*Hc*Dc + d

    // prefetch step 0
    float qn = qpb[tid];
    float kn = kpb[tid];
    float vn = (tid < 64) ? Vb[tid] : 0.f;

    for (int s = 0; s < Sc; s++) {
        q_sh[tid] = qn;
        k_sh[tid] = kn;
        if (tid < 64) v_sh[tid] = vn;
        __syncthreads();

        // prefetch next step (latency hidden behind compute below)
        if (s + 1 < Sc) {
            qn = qpb[(size_t)(s + 1) * Mc + tid];
            kn = kpb[(size_t)(s + 1) * Mc + tid];
            if (tid < 64) vn = Vb[(size_t)(s + 1) * Hc * Dc + tid];
        }

        // ksum update + den partial (thread t owns m = t)
        float ks = ksum_sh[tid] + k_sh[tid];
        ksum_sh[tid] = ks;
        float dp = q_sh[tid] * ks;
        #pragma unroll
        for (int o = 16; o > 0; o >>= 1) dp += __shfl_down_sync(0xffffffffu, dp, o);
        if ((tid & 31) == 0) dred[tid >> 5] = dp;

        // kv update + num partial for this (c,d)
        const float vd = v_sh[d];
        float np = 0.f;
        const float4* k4 = (const float4*)(k_sh + (c << 6));
        const float4* q4 = (const float4*)(q_sh + (c << 6));
        #pragma unroll
        for (int i = 0; i < 16; i++) {
            const float4 kk = k4[i];
            const float4 qq = q4[i];
            kv[4*i + 0] = fmaf(kk.x, vd, kv[4*i + 0]); np = fmaf(kv[4*i + 0], qq.x, np);
            kv[4*i + 1] = fmaf(kk.y, vd, kv[4*i + 1]); np = fmaf(kv[4*i + 1], qq.y, np);
            kv[4*i + 2] = fmaf(kk.z, vd, kv[4*i + 2]); np = fmaf(kv[4*i + 2], qq.z, np);
            kv[4*i + 3] = fmaf(kk.w, vd, kv[4*i + 3]); np = fmaf(kv[4*i + 3], qq.w, np);
        }
        nred[c][d] = np;
        __syncthreads();

        if (tid < 64) {
            const float num = nred[0][tid] + nred[1][tid] + nred[2][tid] + nred[3][tid];
            const float den = dred[0] + dred[1] + dred[2] + dred[3]
                            + dred[4] + dred[5] + dred[6] + dred[7];
            ab[(size_t)s * Hc * Dc + tid] = num / den;
        }
    }
}

// ---------------- layernorm over E per (b,s) row ----------------
__global__ void __launch_bounds__(256)
ln_kernel(const float* __restrict__ res, const float* __restrict__ gamma,
          const float* __restrict__ beta, float* __restrict__ out)
{
    const int row = blockIdx.x;
    const int tid = threadIdx.x;
    const float4 v = *(const float4*)(res + (size_t)row * Ec + tid * 4);
    float s  = v.x + v.y + v.z + v.w;
    float sq = v.x * v.x + v.y * v.y + v.z * v.z + v.w * v.w;
    #pragma unroll
    for (int o = 16; o > 0; o >>= 1) {
        s  += __shfl_down_sync(0xffffffffu, s,  o);
        sq += __shfl_down_sync(0xffffffffu, sq, o);
    }
    __shared__ float ssh[8], sqsh[8];
    __shared__ float s_mu, s_rs;
    if ((tid & 31) == 0) { ssh[tid >> 5] = s; sqsh[tid >> 5] = sq; }
    __syncthreads();
    if (tid == 0) {
        float S = 0.f, Q = 0.f;
        #pragma unroll
        for (int w = 0; w < 8; w++) { S += ssh[w]; Q += sqsh[w]; }
        const float mu  = S * (1.f / Ec);
        const float var = Q * (1.f / Ec) - mu * mu;
        s_mu = mu;
        s_rs = rsqrtf(var + 1e-6f);
    }
    __syncthreads();
    const float mu = s_mu, rs = s_rs;
    const float4 g  = *(const float4*)(gamma + tid * 4);
    const float4 be = *(const float4*)(beta + tid * 4);
    float4 o4;
    o4.x = g.x * (v.x - mu) * rs + be.x;
    o4.y = g.y * (v.y - mu) * rs + be.y;
    o4.z = g.z * (v.z - mu) * rs + be.z;
    o4.w = g.w * (v.w - mu) * rs + be.w;
    *(float4*)(out + (size_t)row * Ec + tid * 4) = o4;
}

// ---------------- launch ----------------
extern "C" void kernel_launch(void* const* d_in, const int* in_sizes, int n_in,
                              void* d_out, int out_size)
{
    const float* x     = (const float*)d_in[0];
    const float* q_w   = (const float*)d_in[1];
    const float* q_b   = (const float*)d_in[2];
    const float* k_w   = (const float*)d_in[3];
    const float* k_b   = (const float*)d_in[4];
    const float* v_w   = (const float*)d_in[5];
    const float* v_b   = (const float*)d_in[6];
    const float* out_w = (const float*)d_in[7];
    const float* out_b = (const float*)d_in[8];
    const float* proj  = (const float*)d_in[9];
    const float* gamma = (const float*)d_in[10];
    const float* beta  = (const float*)d_in[11];
    float* out = (float*)d_out;

    float *Qp, *Kp, *Vp, *qpp, *kpp, *attnp, *resp;
    cudaGetSymbolAddress((void**)&Qp,    g_Q);
    cudaGetSymbolAddress((void**)&Kp,    g_K);
    cudaGetSymbolAddress((void**)&Vp,    g_V);
    cudaGetSymbolAddress((void**)&qpp,   g_qp);
    cudaGetSymbolAddress((void**)&kpp,   g_kp);
    cudaGetSymbolAddress((void**)&attnp, g_attn);
    cudaGetSymbolAddress((void**)&resp,  g_res);

    const dim3 gg(Ec / 128, (Bc * Sc) / 128);        // (8, 64)
    const dim3 gf(Mc / 128, (Bc * Sc * Hc) / 128);   // (2, 1024)

    sgemm_bias<<<gg, 256>>>(x, q_w, q_b, nullptr, Qp, Bc * Sc, Ec, Ec);
    sgemm_bias<<<gg, 256>>>(x, k_w, k_b, nullptr, Kp, Bc * Sc, Ec, Ec);
    sgemm_bias<<<gg, 256>>>(x, v_w, v_b, nullptr, Vp, Bc * Sc, Ec, Ec);

    feature_kernel<<<gf, 256>>>(Qp, proj, qpp);
    feature_kernel<<<gf, 256>>>(Kp, proj, kpp);

    scan_kernel<<<Bc * Hc, 256>>>(qpp, kpp, Vp, attnp);

    sgemm_bias<<<gg, 256>>>(attnp, out_w, out_b, x, resp, Bc * Sc, Ec, Ec);

    ln_kernel<<<Bc * Sc, 256>>>(resp, gamma, beta, out);
}

// round 6
// speedup vs baseline: 1.3694x; 1.3694x over previous
#include <cuda_runtime.h>
#include <cuda_bf16.h>
#include <math.h>
#include <stdint.h>

#define Bc 4
#define Sc 2048
#define Ec 1024
#define Hc 16
#define Mc 256
#define Dc 64
#define GK 1024

typedef unsigned long long u64;

// ---------------- packed f32x2 helpers (Blackwell FFMA2) ----------------
__device__ __forceinline__ u64 ffma2(u64 a, u64 b, u64 c) {
    u64 d;
    asm("fma.rn.f32x2 %0, %1, %2, %3;" : "=l"(d) : "l"(a), "l"(b), "l"(c));
    return d;
}
__device__ __forceinline__ u64 pack2(float x, float y) {
    u64 r;
    asm("mov.b64 %0, {%1, %2};" : "=l"(r) : "f"(x), "f"(y));
    return r;
}
__device__ __forceinline__ float2 unpack2(u64 v) {
    float2 r;
    asm("mov.b64 {%0, %1}, %2;" : "=f"(r.x), "=f"(r.y) : "l"(v));
    return r;
}

__device__ __forceinline__ uint32_t smem_u32(const void* p) {
    uint32_t a;
    asm("{ .reg .u64 t; cvta.to.shared.u64 t, %1; cvt.u32.u64 %0, t; }" : "=r"(a) : "l"(p));
    return a;
}

// bf16 tensor-core mma (sm_80+; compiles under compute_100)
__device__ __forceinline__ void mma_bf16(float* c, const uint32_t* a, const uint32_t* b) {
    asm volatile("mma.sync.aligned.m16n8k16.row.col.f32.bf16.bf16.f32 "
        "{%0,%1,%2,%3}, {%4,%5,%6,%7}, {%8,%9}, {%0,%1,%2,%3};"
        : "+f"(c[0]), "+f"(c[1]), "+f"(c[2]), "+f"(c[3])
        : "r"(a[0]), "r"(a[1]), "r"(a[2]), "r"(a[3]), "r"(b[0]), "r"(b[1]));
}

// ---------------- scratch (device globals; no runtime allocation) ----------------
__device__ float g_Q[Bc*Sc*Ec];
__device__ float g_K[Bc*Sc*Ec];
__device__ float g_V[Bc*Sc*Ec];
__device__ float g_qp[(size_t)Bc*Hc*Sc*Mc];
__device__ float g_kp[(size_t)Bc*Hc*Sc*Mc];
__device__ float g_attn[Bc*Sc*Ec];
__device__ float g_res[Bc*Sc*Ec];
__device__ __nv_bfloat16 g_xh[Bc*Sc*Ec];
__device__ __nv_bfloat16 g_xl[Bc*Sc*Ec];
__device__ __nv_bfloat16 g_ah[Bc*Sc*Ec];
__device__ __nv_bfloat16 g_al[Bc*Sc*Ec];
__device__ __nv_bfloat16 g_wth[4*Ec*Ec];   // transposed hi weights [N,K] x4
__device__ __nv_bfloat16 g_wtl[4*Ec*Ec];   // transposed lo weights

// ---------------- fp32 -> bf16 hi/lo split (elementwise) ----------------
__global__ void __launch_bounds__(256)
split_kernel(const float* __restrict__ in, __nv_bfloat16* __restrict__ hi,
             __nv_bfloat16* __restrict__ lo)
{
    const size_t i = ((size_t)blockIdx.x * 256 + threadIdx.x) * 4;
    const float4 v = *(const float4*)(in + i);
    __nv_bfloat16 h[4], l[4];
    h[0] = __float2bfloat16(v.x); l[0] = __float2bfloat16(v.x - __bfloat162float(h[0]));
    h[1] = __float2bfloat16(v.y); l[1] = __float2bfloat16(v.y - __bfloat162float(h[1]));
    h[2] = __float2bfloat16(v.z); l[2] = __float2bfloat16(v.z - __bfloat162float(h[2]));
    h[3] = __float2bfloat16(v.w); l[3] = __float2bfloat16(v.w - __bfloat162float(h[3]));
    *(uint2*)(hi + i) = *(uint2*)h;
    *(uint2*)(lo + i) = *(uint2*)l;
}

// ---------------- weight transpose + split: W[K,N] -> hiT/loT [N,K] ----------------
__global__ void __launch_bounds__(256)
wsplit_t(const float* __restrict__ W, __nv_bfloat16* __restrict__ hiT,
         __nv_bfloat16* __restrict__ loT)
{
    __shared__ float tile[32][33];
    const int n0 = blockIdx.x * 32;
    const int k0 = blockIdx.y * 32;
    const int tx = threadIdx.x & 31;
    const int ty = threadIdx.x >> 5;   // 0..7
    #pragma unroll
    for (int r = ty; r < 32; r += 8)
        tile[r][tx] = W[(size_t)(k0 + r) * Ec + n0 + tx];
    __syncthreads();
    #pragma unroll
    for (int r = ty; r < 32; r += 8) {
        const float v = tile[tx][r];
        const __nv_bfloat16 h = __float2bfloat16(v);
        const __nv_bfloat16 l = __float2bfloat16(v - __bfloat162float(h));
        const size_t o = (size_t)(n0 + r) * Ec + k0 + tx;
        hiT[o] = h;
        loT[o] = l;
    }
}

// ---------------- bf16-split tensor-core GEMM (mma.sync, cp.async 3-stage) ----------------
// C[8192,1024] = A@B + bias (+add). A via (Ah,Al) K-major bf16; B via (BhT,BlT)=W^T K-major.
// CTA 128x128, BK=32, 8 warps (2m x 4n), warp tile 64x32.
// smem stage layout: 4 tiles (Ah,Al,Bh,Bl), each 128 rows x 64B, XOR-swizzled.
#define STAGE_BYTES 32768
#define LDF(sm, s, tI, row, k) \
    (*(const uint32_t*)((sm) + (s)*STAGE_BYTES + (tI)*8192 + (row)*64 + \
        ((((k) >> 3) ^ ((row) & 3)) << 4) + (((k) & 7) << 1)))

__global__ void __launch_bounds__(256)
bgemm_mma(const __nv_bfloat16* __restrict__ Ah, const __nv_bfloat16* __restrict__ Al,
          const __nv_bfloat16* __restrict__ BhT, const __nv_bfloat16* __restrict__ BlT,
          const float* __restrict__ bias, const float* __restrict__ add,
          float* __restrict__ C)
{
    extern __shared__ __align__(16) char smem[];
    const int tid  = threadIdx.x;
    const int lane = tid & 31;
    const int wid  = tid >> 5;
    const int wm   = wid & 1;        // 0..1 (m)
    const int wn   = wid >> 1;       // 0..3 (n)
    const int gid  = lane >> 2;      // 0..7
    const int tig  = lane & 3;       // 0..3
    const int row0 = blockIdx.y * 128;
    const int col0 = blockIdx.x * 128;
    const uint32_t sb = smem_u32(smem);

    const __nv_bfloat16* gsrc[4] = {
        Ah  + (size_t)row0 * GK, Al  + (size_t)row0 * GK,
        BhT + (size_t)col0 * GK, BlT + (size_t)col0 * GK
    };

    // per-thread cp.async slots: 2 per tile, 4 tiles
    const int r0s = (tid * 2) >> 2,     kc0 = (tid * 2) & 3;
    const int r1s = (tid * 2 + 1) >> 2, kc1 = (tid * 2 + 1) & 3;

    #define LOAD_STAGE(s, k0) do { \
        _Pragma("unroll") \
        for (int tI = 0; tI < 4; tI++) { \
            uint32_t d0 = sb + (s)*STAGE_BYTES + tI*8192 + r0s*64 + ((kc0 ^ (r0s & 3)) << 4); \
            uint32_t d1 = sb + (s)*STAGE_BYTES + tI*8192 + r1s*64 + ((kc1 ^ (r1s & 3)) << 4); \
            const __nv_bfloat16* s0 = gsrc[tI] + (size_t)r0s * GK + (k0) + kc0*8; \
            const __nv_bfloat16* s1 = gsrc[tI] + (size_t)r1s * GK + (k0) + kc1*8; \
            asm volatile("cp.async.cg.shared.global [%0], [%1], 16;" :: "r"(d0), "l"(s0)); \
            asm volatile("cp.async.cg.shared.global [%0], [%1], 16;" :: "r"(d1), "l"(s1)); \
        } \
    } while (0)

    float acc[4][4][4];
    #pragma unroll
    for (int i = 0; i < 4; i++)
        #pragma unroll
        for (int j = 0; j < 4; j++)
            #pragma unroll
            for (int q = 0; q < 4; q++) acc[i][j][q] = 0.f;

    LOAD_STAGE(0, 0);
    asm volatile("cp.async.commit_group;" ::: "memory");
    LOAD_STAGE(1, 32);
    asm volatile("cp.async.commit_group;" ::: "memory");

    const int NT = GK / 32;   // 32
    #pragma unroll 1
    for (int t = 0; t < NT; t++) {
        asm volatile("cp.async.wait_group 1;" ::: "memory");
        __syncthreads();
        if (t + 2 < NT) LOAD_STAGE((t + 2) % 3, (t + 2) * 32);
        asm volatile("cp.async.commit_group;" ::: "memory");

        const int s = t % 3;
        #pragma unroll
        for (int ks = 0; ks < 32; ks += 16) {
            uint32_t ahf[4][4], alf[4][4], bhf[4][2], blf[4][2];
            const int ka = ks + tig * 2;
            #pragma unroll
            for (int mf = 0; mf < 4; mf++) {
                const int ra = wm * 64 + mf * 16 + gid;
                ahf[mf][0] = LDF(smem, s, 0, ra,     ka);
                ahf[mf][1] = LDF(smem, s, 0, ra + 8, ka);
                ahf[mf][2] = LDF(smem, s, 0, ra,     ka + 8);
                ahf[mf][3] = LDF(smem, s, 0, ra + 8, ka + 8);
                alf[mf][0] = LDF(smem, s, 1, ra,     ka);
                alf[mf][1] = LDF(smem, s, 1, ra + 8, ka);
                alf[mf][2] = LDF(smem, s, 1, ra,     ka + 8);
                alf[mf][3] = LDF(smem, s, 1, ra + 8, ka + 8);
            }
            #pragma unroll
            for (int nf = 0; nf < 4; nf++) {
                const int rb = wn * 32 + nf * 8 + gid;
                bhf[nf][0] = LDF(smem, s, 2, rb, ka);
                bhf[nf][1] = LDF(smem, s, 2, rb, ka + 8);
                blf[nf][0] = LDF(smem, s, 3, rb, ka);
                blf[nf][1] = LDF(smem, s, 3, rb, ka + 8);
            }
            #pragma unroll
            for (int mf = 0; mf < 4; mf++)
                #pragma unroll
                for (int nf = 0; nf < 4; nf++) {
                    mma_bf16(acc[mf][nf], ahf[mf], bhf[nf]);
                    mma_bf16(acc[mf][nf], ahf[mf], blf[nf]);
                    mma_bf16(acc[mf][nf], alf[mf], bhf[nf]);
                }
        }
    }

    // epilogue: c0,c1 -> (row, col..col+1); c2,c3 -> (row+8, ...)
    #pragma unroll
    for (int mf = 0; mf < 4; mf++) {
        const int row = row0 + wm * 64 + mf * 16 + gid;
        #pragma unroll
        for (int nf = 0; nf < 4; nf++) {
            const int col = col0 + wn * 32 + nf * 8 + tig * 2;
            const float b0 = __ldg(bias + col);
            const float b1 = __ldg(bias + col + 1);
            float2 v0, v1;
            v0.x = acc[mf][nf][0] + b0; v0.y = acc[mf][nf][1] + b1;
            v1.x = acc[mf][nf][2] + b0; v1.y = acc[mf][nf][3] + b1;
            const size_t o0 = (size_t)row * Ec + col;
            const size_t o1 = (size_t)(row + 8) * Ec + col;
            if (add) {
                const float2 a0 = *(const float2*)(add + o0);
                const float2 a1 = *(const float2*)(add + o1);
                v0.x += a0.x; v0.y += a0.y;
                v1.x += a1.x; v1.y += a1.y;
            }
            *(float2*)(C + o0) = v0;
            *(float2*)(C + o1) = v1;
        }
    }
}

// ---------------- feature map (FFMA2) ----------------
__global__ void __launch_bounds__(256)
feature_kernel(const float* __restrict__ A, const float* __restrict__ proj,
               float* __restrict__ out)
{
    __shared__ __align__(16) float As[16][128];
    __shared__ __align__(16) float Bs[16][128];
    __shared__ float s2[128][2];
    const int tid  = threadIdx.x;
    const int tx   = tid & 15;
    const int ty   = tid >> 4;
    const int row0 = blockIdx.y * 128;
    const int col0 = blockIdx.x * 128;

    {
        int r = tid >> 1, half = tid & 1;
        const float* p = A + (size_t)(row0 + r) * Dc + half * 32;
        float s = 0.f;
        #pragma unroll
        for (int i = 0; i < 32; i++) s = fmaf(p[i], p[i], s);
        s2[r][half] = s;
    }

    u64 acc[8][4];
    #pragma unroll
    for (int i = 0; i < 8; i++)
        #pragma unroll
        for (int j = 0; j < 4; j++) acc[i][j] = 0ull;

    for (int k0 = 0; k0 < Dc; k0 += 16) {
        #pragma unroll
        for (int i = 0; i < 2; i++) {
            int id = (tid << 1) + i;
            int r  = id >> 2;
            int kc = (id & 3) << 2;
            const float4 a = *(const float4*)(A + (size_t)(row0 + r) * Dc + k0 + kc);
            As[kc + 0][r] = a.x;
            As[kc + 1][r] = a.y;
            As[kc + 2][r] = a.z;
            As[kc + 3][r] = a.w;
            int kr = id >> 5;
            int nc = (id & 31) << 2;
            Bs[kr][nc + 0] = proj[(size_t)(col0 + nc + 0) * Dc + k0 + kr];
            Bs[kr][nc + 1] = proj[(size_t)(col0 + nc + 1) * Dc + k0 + kr];
            Bs[kr][nc + 2] = proj[(size_t)(col0 + nc + 2) * Dc + k0 + kr];
            Bs[kr][nc + 3] = proj[(size_t)(col0 + nc + 3) * Dc + k0 + kr];
        }
        __syncthreads();
        #pragma unroll
        for (int k = 0; k < 16; k++) {
            float4 a0 = *(const float4*)(&As[k][ty * 8]);
            float4 a1 = *(const float4*)(&As[k][ty * 8 + 4]);
            ulonglong2 b0 = *(const ulonglong2*)(&Bs[k][tx * 8]);
            ulonglong2 b1 = *(const ulonglong2*)(&Bs[k][tx * 8 + 4]);
            u64 rb[4] = { b0.x, b0.y, b1.x, b1.y };
            u64 ra[8] = { pack2(a0.x, a0.x), pack2(a0.y, a0.y),
                          pack2(a0.z, a0.z), pack2(a0.w, a0.w),
                          pack2(a1.x, a1.x), pack2(a1.y, a1.y),
                          pack2(a1.z, a1.z), pack2(a1.w, a1.w) };
            #pragma unroll
            for (int i = 0; i < 8; i++)
                #pragma unroll
                for (int j = 0; j < 4; j++)
                    acc[i][j] = ffma2(ra[i], rb[j], acc[i][j]);
        }
        __syncthreads();
    }

    #pragma unroll
    for (int i = 0; i < 8; i++) {
        const int rr = ty * 8 + i;
        const int r  = row0 + rr;
        const float ss = s2[rr][0] + s2[rr][1];
        const int b = r >> 15;
        const int s = (r >> 4) & (Sc - 1);
        const int h = r & (Hc - 1);
        const size_t obase = ((size_t)(b * Hc + h) * Sc + s) * Mc + col0 + tx * 8;
        const float corr = ss * (1.f / 128.f);
        float vals[8];
        const float2 v0 = unpack2(acc[i][0]);
        const float2 v1 = unpack2(acc[i][1]);
        const float2 v2 = unpack2(acc[i][2]);
        const float2 v3 = unpack2(acc[i][3]);
        vals[0] = v0.x; vals[1] = v0.y; vals[2] = v1.x; vals[3] = v1.y;
        vals[4] = v2.x; vals[5] = v2.y; vals[6] = v3.x; vals[7] = v3.y;
        #pragma unroll
        for (int j = 0; j < 8; j++)
            out[obase + j] = 0.0625f * expf(fmaf(vals[j], 0.125f, -corr));
    }
}

// ---------------- causal linear-attention scan (FFMA2) ----------------
__global__ void __launch_bounds__(256)
scan_kernel(const float* __restrict__ qp, const float* __restrict__ kp,
            const float* __restrict__ V, float* __restrict__ attn)
{
    const int bh  = blockIdx.x;
    const int b   = bh >> 4;
    const int h   = bh & 15;
    const int tid = threadIdx.x;
    const int c   = tid >> 6;
    const int d   = tid & 63;

    __shared__ __align__(16) float q_sh[256];
    __shared__ __align__(16) float k_sh[256];
    __shared__ float v_sh[64];
    __shared__ float ksum_sh[256];
    __shared__ float nred[4][64];
    __shared__ float dred[8];

    u64 kv[32];
    #pragma unroll
    for (int i = 0; i < 32; i++) kv[i] = 0ull;
    ksum_sh[tid] = 0.f;

    const float* qpb = qp + (size_t)bh * Sc * Mc;
    const float* kpb = kp + (size_t)bh * Sc * Mc;
    const float* Vb  = V + ((size_t)b * Sc * Hc + h) * Dc;
    float*       ab  = attn + ((size_t)b * Sc * Hc + h) * Dc;

    float qn = qpb[tid];
    float kn = kpb[tid];
    float vn = (tid < 64) ? Vb[tid] : 0.f;

    for (int s = 0; s < Sc; s++) {
        q_sh[tid] = qn;
        k_sh[tid] = kn;
        if (tid < 64) v_sh[tid] = vn;
        __syncthreads();

        if (s + 1 < Sc) {
            qn = qpb[(size_t)(s + 1) * Mc + tid];
            kn = kpb[(size_t)(s + 1) * Mc + tid];
            if (tid < 64) vn = Vb[(size_t)(s + 1) * Hc * Dc + tid];
        }

        float ks = ksum_sh[tid] + k_sh[tid];
        ksum_sh[tid] = ks;
        float dp = q_sh[tid] * ks;
        #pragma unroll
        for (int o = 16; o > 0; o >>= 1) dp += __shfl_down_sync(0xffffffffu, dp, o);
        if ((tid & 31) == 0) dred[tid >> 5] = dp;

        const u64 vd2 = pack2(v_sh[d], v_sh[d]);
        u64 np0 = 0ull, np1 = 0ull;
        const ulonglong2* k4 = (const ulonglong2*)(k_sh + (c << 6));
        const ulonglong2* q4 = (const ulonglong2*)(q_sh + (c << 6));
        #pragma unroll
        for (int i = 0; i < 16; i++) {
            const ulonglong2 kk = k4[i];
            const ulonglong2 qq = q4[i];
            kv[2*i + 0] = ffma2(kk.x, vd2, kv[2*i + 0]);
            np0 = ffma2(kv[2*i + 0], qq.x, np0);
            kv[2*i + 1] = ffma2(kk.y, vd2, kv[2*i + 1]);
            np1 = ffma2(kv[2*i + 1], qq.y, np1);
        }
        const float2 n0 = unpack2(np0);
        const float2 n1 = unpack2(np1);
        nred[c][d] = (n0.x + n0.y) + (n1.x + n1.y);
        __syncthreads();

        if (tid < 64) {
            const float num = nred[0][tid] + nred[1][tid] + nred[2][tid] + nred[3][tid];
            const float den = dred[0] + dred[1] + dred[2] + dred[3]
                            + dred[4] + dred[5] + dred[6] + dred[7];
            ab[(size_t)s * Hc * Dc + tid] = num / den;
        }
    }
}

// ---------------- layernorm ----------------
__global__ void __launch_bounds__(256)
ln_kernel(const float* __restrict__ res, const float* __restrict__ gamma,
          const float* __restrict__ beta, float* __restrict__ out)
{
    const int row = blockIdx.x;
    const int tid = threadIdx.x;
    const float4 v = *(const float4*)(res + (size_t)row * Ec + tid * 4);
    float s  = v.x + v.y + v.z + v.w;
    float sq = v.x * v.x + v.y * v.y + v.z * v.z + v.w * v.w;
    #pragma unroll
    for (int o = 16; o > 0; o >>= 1) {
        s  += __shfl_down_sync(0xffffffffu, s,  o);
        sq += __shfl_down_sync(0xffffffffu, sq, o);
    }
    __shared__ float ssh[8], sqsh[8];
    __shared__ float s_mu, s_rs;
    if ((tid & 31) == 0) { ssh[tid >> 5] = s; sqsh[tid >> 5] = sq; }
    __syncthreads();
    if (tid == 0) {
        float S = 0.f, Q = 0.f;
        #pragma unroll
        for (int w = 0; w < 8; w++) { S += ssh[w]; Q += sqsh[w]; }
        const float mu  = S * (1.f / Ec);
        const float var = Q * (1.f / Ec) - mu * mu;
        s_mu = mu;
        s_rs = rsqrtf(var + 1e-6f);
    }
    __syncthreads();
    const float mu = s_mu, rs = s_rs;
    const float4 g  = *(const float4*)(gamma + tid * 4);
    const float4 be = *(const float4*)(beta + tid * 4);
    float4 o4;
    o4.x = g.x * (v.x - mu) * rs + be.x;
    o4.y = g.y * (v.y - mu) * rs + be.y;
    o4.z = g.z * (v.z - mu) * rs + be.z;
    o4.w = g.w * (v.w - mu) * rs + be.w;
    *(float4*)(out + (size_t)row * Ec + tid * 4) = o4;
}

// ---------------- launch ----------------
extern "C" void kernel_launch(void* const* d_in, const int* in_sizes, int n_in,
                              void* d_out, int out_size)
{
    const float* x     = (const float*)d_in[0];
    const float* q_w   = (const float*)d_in[1];
    const float* q_b   = (const float*)d_in[2];
    const float* k_w   = (const float*)d_in[3];
    const float* k_b   = (const float*)d_in[4];
    const float* v_w   = (const float*)d_in[5];
    const float* v_b   = (const float*)d_in[6];
    const float* out_w = (const float*)d_in[7];
    const float* out_b = (const float*)d_in[8];
    const float* proj  = (const float*)d_in[9];
    const float* gamma = (const float*)d_in[10];
    const float* beta  = (const float*)d_in[11];
    float* out = (float*)d_out;

    float *Qp, *Kp, *Vp, *qpp, *kpp, *attnp, *resp;
    __nv_bfloat16 *xh, *xl, *ah, *al, *wth, *wtl;
    cudaGetSymbolAddress((void**)&Qp,    g_Q);
    cudaGetSymbolAddress((void**)&Kp,    g_K);
    cudaGetSymbolAddress((void**)&Vp,    g_V);
    cudaGetSymbolAddress((void**)&qpp,   g_qp);
    cudaGetSymbolAddress((void**)&kpp,   g_kp);
    cudaGetSymbolAddress((void**)&attnp, g_attn);
    cudaGetSymbolAddress((void**)&resp,  g_res);
    cudaGetSymbolAddress((void**)&xh,    g_xh);
    cudaGetSymbolAddress((void**)&xl,    g_xl);
    cudaGetSymbolAddress((void**)&ah,    g_ah);
    cudaGetSymbolAddress((void**)&al,    g_al);
    cudaGetSymbolAddress((void**)&wth,   g_wth);
    cudaGetSymbolAddress((void**)&wtl,   g_wtl);

    cudaFuncSetAttribute(bgemm_mma, cudaFuncAttributeMaxDynamicSharedMemorySize, 98304);

    const int NE = Bc * Sc * Ec;                 // 8388608
    const dim3 gw(32, 32);
    const dim3 gb(Ec / 128, (Bc * Sc) / 128);    // (8, 64)
    const dim3 gf(Mc / 128, (Bc * Sc * Hc) / 128);

    split_kernel<<<NE / 1024, 256>>>(x, xh, xl);
    wsplit_t<<<gw, 256>>>(q_w,   wth + 0 * Ec * Ec, wtl + 0 * Ec * Ec);
    wsplit_t<<<gw, 256>>>(k_w,   wth + 1 * Ec * Ec, wtl + 1 * Ec * Ec);
    wsplit_t<<<gw, 256>>>(v_w,   wth + 2 * Ec * Ec, wtl + 2 * Ec * Ec);
    wsplit_t<<<gw, 256>>>(out_w, wth + 3 * Ec * Ec, wtl + 3 * Ec * Ec);

    bgemm_mma<<<gb, 256, 98304>>>(xh, xl, wth + 0 * Ec * Ec, wtl + 0 * Ec * Ec, q_b, nullptr, Qp);
    bgemm_mma<<<gb, 256, 98304>>>(xh, xl, wth + 1 * Ec * Ec, wtl + 1 * Ec * Ec, k_b, nullptr, Kp);
    bgemm_mma<<<gb, 256, 98304>>>(xh, xl, wth + 2 * Ec * Ec, wtl + 2 * Ec * Ec, v_b, nullptr, Vp);

    feature_kernel<<<gf, 256>>>(Qp, proj, qpp);
    feature_kernel<<<gf, 256>>>(Kp, proj, kpp);

    scan_kernel<<<Bc * Hc, 256>>>(qpp, kpp, Vp, attnp);

    split_kernel<<<NE / 1024, 256>>>(attnp, ah, al);
    bgemm_mma<<<gb, 256, 98304>>>(ah, al, wth + 3 * Ec * Ec, wtl + 3 * Ec * Ec, out_b, x, resp);

    ln_kernel<<<Bc * Sc, 256>>>(resp, gamma, beta, out);
}

// round 7
// speedup vs baseline: 1.4285x; 1.0431x over previous
#include <cuda_runtime.h>
#include <cuda_bf16.h>
#include <math.h>
#include <stdint.h>

#define Bc 4
#define Sc 2048
#define Ec 1024
#define Hc 16
#define Mc 256
#define Dc 64
#define GK 1024

typedef unsigned long long u64;

// ---------------- packed f32x2 helpers (Blackwell FFMA2) ----------------
__device__ __forceinline__ u64 ffma2(u64 a, u64 b, u64 c) {
    u64 d;
    asm("fma.rn.f32x2 %0, %1, %2, %3;" : "=l"(d) : "l"(a), "l"(b), "l"(c));
    return d;
}
__device__ __forceinline__ u64 pack2(float x, float y) {
    u64 r;
    asm("mov.b64 %0, {%1, %2};" : "=l"(r) : "f"(x), "f"(y));
    return r;
}
__device__ __forceinline__ float2 unpack2(u64 v) {
    float2 r;
    asm("mov.b64 {%0, %1}, %2;" : "=f"(r.x), "=f"(r.y) : "l"(v));
    return r;
}

__device__ __forceinline__ uint32_t smem_u32(const void* p) {
    uint32_t a;
    asm("{ .reg .u64 t; cvta.to.shared.u64 t, %1; cvt.u32.u64 %0, t; }" : "=r"(a) : "l"(p));
    return a;
}

// bf16 tensor-core mma (sm_80+)
__device__ __forceinline__ void mma_bf16(float* c, const uint32_t* a, const uint32_t* b) {
    asm volatile("mma.sync.aligned.m16n8k16.row.col.f32.bf16.bf16.f32 "
        "{%0,%1,%2,%3}, {%4,%5,%6,%7}, {%8,%9}, {%0,%1,%2,%3};"
        : "+f"(c[0]), "+f"(c[1]), "+f"(c[2]), "+f"(c[3])
        : "r"(a[0]), "r"(a[1]), "r"(a[2]), "r"(a[3]), "r"(b[0]), "r"(b[1]));
}

#define LDSM4(r0, r1, r2, r3, addr) \
    asm volatile("ldmatrix.sync.aligned.m8n8.x4.shared.b16 {%0,%1,%2,%3}, [%4];" \
        : "=r"(r0), "=r"(r1), "=r"(r2), "=r"(r3) : "r"(addr))

// ---------------- scratch (device globals; no runtime allocation) ----------------
__device__ float g_Q[Bc*Sc*Ec];
__device__ float g_K[Bc*Sc*Ec];
__device__ float g_V[Bc*Sc*Ec];
__device__ float g_qp[(size_t)Bc*Hc*Sc*Mc];
__device__ float g_kp[(size_t)Bc*Hc*Sc*Mc];
__device__ float g_attn[Bc*Sc*Ec];
__device__ float g_res[Bc*Sc*Ec];
__device__ __nv_bfloat16 g_xh[Bc*Sc*Ec];
__device__ __nv_bfloat16 g_xl[Bc*Sc*Ec];
__device__ __nv_bfloat16 g_ah[Bc*Sc*Ec];
__device__ __nv_bfloat16 g_al[Bc*Sc*Ec];
__device__ __nv_bfloat16 g_wth[4*Ec*Ec];   // transposed hi weights [N,K] x4
__device__ __nv_bfloat16 g_wtl[4*Ec*Ec];   // transposed lo weights

// ---------------- fp32 -> bf16 hi/lo split (elementwise) ----------------
__global__ void __launch_bounds__(256)
split_kernel(const float* __restrict__ in, __nv_bfloat16* __restrict__ hi,
             __nv_bfloat16* __restrict__ lo)
{
    const size_t i = ((size_t)blockIdx.x * 256 + threadIdx.x) * 4;
    const float4 v = *(const float4*)(in + i);
    __nv_bfloat16 h[4], l[4];
    h[0] = __float2bfloat16(v.x); l[0] = __float2bfloat16(v.x - __bfloat162float(h[0]));
    h[1] = __float2bfloat16(v.y); l[1] = __float2bfloat16(v.y - __bfloat162float(h[1]));
    h[2] = __float2bfloat16(v.z); l[2] = __float2bfloat16(v.z - __bfloat162float(h[2]));
    h[3] = __float2bfloat16(v.w); l[3] = __float2bfloat16(v.w - __bfloat162float(h[3]));
    *(uint2*)(hi + i) = *(uint2*)h;
    *(uint2*)(lo + i) = *(uint2*)l;
}

// ---------------- weight transpose + split: W[K,N] -> hiT/loT [N,K] ----------------
__global__ void __launch_bounds__(256)
wsplit_t(const float* __restrict__ W, __nv_bfloat16* __restrict__ hiT,
         __nv_bfloat16* __restrict__ loT)
{
    __shared__ float tile[32][33];
    const int n0 = blockIdx.x * 32;
    const int k0 = blockIdx.y * 32;
    const int tx = threadIdx.x & 31;
    const int ty = threadIdx.x >> 5;   // 0..7
    #pragma unroll
    for (int r = ty; r < 32; r += 8)
        tile[r][tx] = W[(size_t)(k0 + r) * Ec + n0 + tx];
    __syncthreads();
    #pragma unroll
    for (int r = ty; r < 32; r += 8) {
        const float v = tile[tx][r];
        const __nv_bfloat16 h = __float2bfloat16(v);
        const __nv_bfloat16 l = __float2bfloat16(v - __bfloat162float(h));
        const size_t o = (size_t)(n0 + r) * Ec + k0 + tx;
        hiT[o] = h;
        loT[o] = l;
    }
}

// ---------------- bf16-split tensor-core GEMM (mma.sync + ldmatrix, cp.async 3-stage) ----
// C[8192,1024] = A@B + bias (+add). Tiles: CTA 128x128, BK=32, 8 warps (2m x 4n).
// smem stage: 4 tiles (Ah,Al,Bh,Bl), each 128 rows x 64B.
// Swizzle: 16B chunk index c = ((row>>1)&3) ^ kc  -> conflict-free ldmatrix phases.
#define STAGE_BYTES 32768

__global__ void __launch_bounds__(256)
bgemm_mma(const __nv_bfloat16* __restrict__ Ah, const __nv_bfloat16* __restrict__ Al,
          const __nv_bfloat16* __restrict__ BhT, const __nv_bfloat16* __restrict__ BlT,
          const float* __restrict__ bias, const float* __restrict__ add,
          float* __restrict__ C)
{
    extern __shared__ __align__(16) char smem[];
    const int tid  = threadIdx.x;
    const int lane = tid & 31;
    const int wid  = tid >> 5;
    const int wm   = wid & 1;        // 0..1 (m)
    const int wn   = wid >> 1;       // 0..3 (n)
    const int gid  = lane >> 2;      // 0..7
    const int tig  = lane & 3;       // 0..3
    const int row0 = blockIdx.y * 128;
    const int col0 = blockIdx.x * 128;
    const uint32_t sb = smem_u32(smem);

    // ldmatrix lane->address mapping
    const int matq   = lane >> 3;                     // 0..3 (which 8x8 matrix)
    const int rA_off = ((matq & 1) << 3) | (lane & 7); // A: mat0/2 rows0-7, mat1/3 rows8-15
    const int kcA    = matq >> 1;                      // A: mat0/1 kc+0, mat2/3 kc+1
    const int rB_off = ((matq >> 1) << 3) | (lane & 7);// B: mat0/1 rows0-7, mat2/3 rows8-15
    const int kcB    = matq & 1;                       // B: mat0/2 kc+0, mat1/3 kc+1
    const int cA     = (rA_off >> 1) & 3;
    const int cB     = (rB_off >> 1) & 3;

    const __nv_bfloat16* gsrc[4] = {
        Ah  + (size_t)row0 * GK, Al  + (size_t)row0 * GK,
        BhT + (size_t)col0 * GK, BlT + (size_t)col0 * GK
    };

    // cp.async slots: id = tid*2 + i; row = id>>2, kc = id&3
    const int r0s = (tid * 2) >> 2,     kc0 = (tid * 2) & 3;
    const int r1s = (tid * 2 + 1) >> 2, kc1 = (tid * 2 + 1) & 3;
    const int c0s = ((r0s >> 1) & 3) ^ kc0;
    const int c1s = ((r1s >> 1) & 3) ^ kc1;

    #define LOAD_STAGE(s, k0) do { \
        _Pragma("unroll") \
        for (int tI = 0; tI < 4; tI++) { \
            uint32_t d0 = sb + (s)*STAGE_BYTES + tI*8192 + r0s*64 + (c0s << 4); \
            uint32_t d1 = sb + (s)*STAGE_BYTES + tI*8192 + r1s*64 + (c1s << 4); \
            const __nv_bfloat16* s0 = gsrc[tI] + (size_t)r0s * GK + (k0) + kc0*8; \
            const __nv_bfloat16* s1 = gsrc[tI] + (size_t)r1s * GK + (k0) + kc1*8; \
            asm volatile("cp.async.cg.shared.global [%0], [%1], 16;" :: "r"(d0), "l"(s0)); \
            asm volatile("cp.async.cg.shared.global [%0], [%1], 16;" :: "r"(d1), "l"(s1)); \
        } \
    } while (0)

    float acc[4][4][4];
    #pragma unroll
    for (int i = 0; i < 4; i++)
        #pragma unroll
        for (int j = 0; j < 4; j++)
            #pragma unroll
            for (int q = 0; q < 4; q++) acc[i][j][q] = 0.f;

    LOAD_STAGE(0, 0);
    asm volatile("cp.async.commit_group;" ::: "memory");
    LOAD_STAGE(1, 32);
    asm volatile("cp.async.commit_group;" ::: "memory");

    const int NT = GK / 32;   // 32
    #pragma unroll 1
    for (int t = 0; t < NT; t++) {
        asm volatile("cp.async.wait_group 1;" ::: "memory");
        __syncthreads();
        if (t + 2 < NT) LOAD_STAGE((t + 2) % 3, (t + 2) * 32);
        asm volatile("cp.async.commit_group;" ::: "memory");

        const uint32_t sbS = sb + (t % 3) * STAGE_BYTES;
        #pragma unroll
        for (int ks = 0; ks < 32; ks += 16) {
            const int kb = ks >> 3;
            // B fragments: 2 nf-pairs x (hi, lo)
            uint32_t bh[4][2], bl[4][2];
            #pragma unroll
            for (int p = 0; p < 2; p++) {
                const uint32_t baddr = sbS + 2*8192 +
                    (uint32_t)(wn * 32 + p * 16 + rB_off) * 64 + ((cB ^ (kb + kcB)) << 4);
                LDSM4(bh[2*p][0], bh[2*p][1], bh[2*p+1][0], bh[2*p+1][1], baddr);
                LDSM4(bl[2*p][0], bl[2*p][1], bl[2*p+1][0], bl[2*p+1][1], baddr + 8192);
            }
            #pragma unroll
            for (int mf = 0; mf < 4; mf++) {
                uint32_t ah[4], al[4];
                const uint32_t aaddr = sbS +
                    (uint32_t)(wm * 64 + mf * 16 + rA_off) * 64 + ((cA ^ (kb + kcA)) << 4);
                LDSM4(ah[0], ah[1], ah[2], ah[3], aaddr);
                LDSM4(al[0], al[1], al[2], al[3], aaddr + 8192);
                #pragma unroll
                for (int nf = 0; nf < 4; nf++) mma_bf16(acc[mf][nf], ah, bh[nf]);
                #pragma unroll
                for (int nf = 0; nf < 4; nf++) mma_bf16(acc[mf][nf], ah, bl[nf]);
                #pragma unroll
                for (int nf = 0; nf < 4; nf++) mma_bf16(acc[mf][nf], al, bh[nf]);
            }
        }
    }

    // epilogue: c0,c1 -> (row, col..col+1); c2,c3 -> (row+8, ...)
    #pragma unroll
    for (int mf = 0; mf < 4; mf++) {
        const int row = row0 + wm * 64 + mf * 16 + gid;
        #pragma unroll
        for (int nf = 0; nf < 4; nf++) {
            const int col = col0 + wn * 32 + nf * 8 + tig * 2;
            const float b0 = __ldg(bias + col);
            const float b1 = __ldg(bias + col + 1);
            float2 v0, v1;
            v0.x = acc[mf][nf][0] + b0; v0.y = acc[mf][nf][1] + b1;
            v1.x = acc[mf][nf][2] + b0; v1.y = acc[mf][nf][3] + b1;
            const size_t o0 = (size_t)row * Ec + col;
            const size_t o1 = (size_t)(row + 8) * Ec + col;
            if (add) {
                const float2 a0 = *(const float2*)(add + o0);
                const float2 a1 = *(const float2*)(add + o1);
                v0.x += a0.x; v0.y += a0.y;
                v1.x += a1.x; v1.y += a1.y;
            }
            *(float2*)(C + o0) = v0;
            *(float2*)(C + o1) = v1;
        }
    }
}

// ---------------- feature map (FFMA2) ----------------
__global__ void __launch_bounds__(256)
feature_kernel(const float* __restrict__ A, const float* __restrict__ proj,
               float* __restrict__ out)
{
    __shared__ __align__(16) float As[16][128];
    __shared__ __align__(16) float Bs[16][128];
    __shared__ float s2[128][2];
    const int tid  = threadIdx.x;
    const int tx   = tid & 15;
    const int ty   = tid >> 4;
    const int row0 = blockIdx.y * 128;
    const int col0 = blockIdx.x * 128;

    {
        int r = tid >> 1, half = tid & 1;
        const float* p = A + (size_t)(row0 + r) * Dc + half * 32;
        float s = 0.f;
        #pragma unroll
        for (int i = 0; i < 32; i++) s = fmaf(p[i], p[i], s);
        s2[r][half] = s;
    }

    u64 acc[8][4];
    #pragma unroll
    for (int i = 0; i < 8; i++)
        #pragma unroll
        for (int j = 0; j < 4; j++) acc[i][j] = 0ull;

    for (int k0 = 0; k0 < Dc; k0 += 16) {
        #pragma unroll
        for (int i = 0; i < 2; i++) {
            int id = (tid << 1) + i;
            int r  = id >> 2;
            int kc = (id & 3) << 2;
            const float4 a = *(const float4*)(A + (size_t)(row0 + r) * Dc + k0 + kc);
            As[kc + 0][r] = a.x;
            As[kc + 1][r] = a.y;
            As[kc + 2][r] = a.z;
            As[kc + 3][r] = a.w;
            int kr = id >> 5;
            int nc = (id & 31) << 2;
            Bs[kr][nc + 0] = proj[(size_t)(col0 + nc + 0) * Dc + k0 + kr];
            Bs[kr][nc + 1] = proj[(size_t)(col0 + nc + 1) * Dc + k0 + kr];
            Bs[kr][nc + 2] = proj[(size_t)(col0 + nc + 2) * Dc + k0 + kr];
            Bs[kr][nc + 3] = proj[(size_t)(col0 + nc + 3) * Dc + k0 + kr];
        }
        __syncthreads();
        #pragma unroll
        for (int k = 0; k < 16; k++) {
            float4 a0 = *(const float4*)(&As[k][ty * 8]);
            float4 a1 = *(const float4*)(&As[k][ty * 8 + 4]);
            ulonglong2 b0 = *(const ulonglong2*)(&Bs[k][tx * 8]);
            ulonglong2 b1 = *(const ulonglong2*)(&Bs[k][tx * 8 + 4]);
            u64 rb[4] = { b0.x, b0.y, b1.x, b1.y };
            u64 ra[8] = { pack2(a0.x, a0.x), pack2(a0.y, a0.y),
                          pack2(a0.z, a0.z), pack2(a0.w, a0.w),
                          pack2(a1.x, a1.x), pack2(a1.y, a1.y),
                          pack2(a1.z, a1.z), pack2(a1.w, a1.w) };
            #pragma unroll
            for (int i = 0; i < 8; i++)
                #pragma unroll
                for (int j = 0; j < 4; j++)
                    acc[i][j] = ffma2(ra[i], rb[j], acc[i][j]);
        }
        __syncthreads();
    }

    #pragma unroll
    for (int i = 0; i < 8; i++) {
        const int rr = ty * 8 + i;
        const int r  = row0 + rr;
        const float ss = s2[rr][0] + s2[rr][1];
        const int b = r >> 15;
        const int s = (r >> 4) & (Sc - 1);
        const int h = r & (Hc - 1);
        const size_t obase = ((size_t)(b * Hc + h) * Sc + s) * Mc + col0 + tx * 8;
        const float corr = ss * (1.f / 128.f);
        float vals[8];
        const float2 v0 = unpack2(acc[i][0]);
        const float2 v1 = unpack2(acc[i][1]);
        const float2 v2 = unpack2(acc[i][2]);
        const float2 v3 = unpack2(acc[i][3]);
        vals[0] = v0.x; vals[1] = v0.y; vals[2] = v1.x; vals[3] = v1.y;
        vals[4] = v2.x; vals[5] = v2.y; vals[6] = v3.x; vals[7] = v3.y;
        #pragma unroll
        for (int j = 0; j < 8; j++)
            out[obase + j] = 0.0625f * expf(fmaf(vals[j], 0.125f, -corr));
    }
}

// ---------------- causal linear-attention scan (FFMA2) ----------------
__global__ void __launch_bounds__(256)
scan_kernel(const float* __restrict__ qp, const float* __restrict__ kp,
            const float* __restrict__ V, float* __restrict__ attn)
{
    const int bh  = blockIdx.x;
    const int b   = bh >> 4;
    const int h   = bh & 15;
    const int tid = threadIdx.x;
    const int c   = tid >> 6;
    const int d   = tid & 63;

    __shared__ __align__(16) float q_sh[256];
    __shared__ __align__(16) float k_sh[256];
    __shared__ float v_sh[64];
    __shared__ float ksum_sh[256];
    __shared__ float nred[4][64];
    __shared__ float dred[8];

    u64 kv[32];
    #pragma unroll
    for (int i = 0; i < 32; i++) kv[i] = 0ull;
    ksum_sh[tid] = 0.f;

    const float* qpb = qp + (size_t)bh * Sc * Mc;
    const float* kpb = kp + (size_t)bh * Sc * Mc;
    const float* Vb  = V + ((size_t)b * Sc * Hc + h) * Dc;
    float*       ab  = attn + ((size_t)b * Sc * Hc + h) * Dc;

    float qn = qpb[tid];
    float kn = kpb[tid];
    float vn = (tid < 64) ? Vb[tid] : 0.f;

    for (int s = 0; s < Sc; s++) {
        q_sh[tid] = qn;
        k_sh[tid] = kn;
        if (tid < 64) v_sh[tid] = vn;
        __syncthreads();

        if (s + 1 < Sc) {
            qn = qpb[(size_t)(s + 1) * Mc + tid];
            kn = kpb[(size_t)(s + 1) * Mc + tid];
            if (tid < 64) vn = Vb[(size_t)(s + 1) * Hc * Dc + tid];
        }

        float ks = ksum_sh[tid] + k_sh[tid];
        ksum_sh[tid] = ks;
        float dp = q_sh[tid] * ks;
        #pragma unroll
        for (int o = 16; o > 0; o >>= 1) dp += __shfl_down_sync(0xffffffffu, dp, o);
        if ((tid & 31) == 0) dred[tid >> 5] = dp;

        const u64 vd2 = pack2(v_sh[d], v_sh[d]);
        u64 np0 = 0ull, np1 = 0ull;
        const ulonglong2* k4 = (const ulonglong2*)(k_sh + (c << 6));
        const ulonglong2* q4 = (const ulonglong2*)(q_sh + (c << 6));
        #pragma unroll
        for (int i = 0; i < 16; i++) {
            const ulonglong2 kk = k4[i];
            const ulonglong2 qq = q4[i];
            kv[2*i + 0] = ffma2(kk.x, vd2, kv[2*i + 0]);
            np0 = ffma2(kv[2*i + 0], qq.x, np0);
            kv[2*i + 1] = ffma2(kk.y, vd2, kv[2*i + 1]);
            np1 = ffma2(kv[2*i + 1], qq.y, np1);
        }
        const float2 n0 = unpack2(np0);
        const float2 n1 = unpack2(np1);
        nred[c][d] = (n0.x + n0.y) + (n1.x + n1.y);
        __syncthreads();

        if (tid < 64) {
            const float num = nred[0][tid] + nred[1][tid] + nred[2][tid] + nred[3][tid];
            const float den = dred[0] + dred[1] + dred[2] + dred[3]
                            + dred[4] + dred[5] + dred[6] + dred[7];
            ab[(size_t)s * Hc * Dc + tid] = num / den;
        }
    }
}

// ---------------- layernorm ----------------
__global__ void __launch_bounds__(256)
ln_kernel(const float* __restrict__ res, const float* __restrict__ gamma,
          const float* __restrict__ beta, float* __restrict__ out)
{
    const int row = blockIdx.x;
    const int tid = threadIdx.x;
    const float4 v = *(const float4*)(res + (size_t)row * Ec + tid * 4);
    float s  = v.x + v.y + v.z + v.w;
    float sq = v.x * v.x + v.y * v.y + v.z * v.z + v.w * v.w;
    #pragma unroll
    for (int o = 16; o > 0; o >>= 1) {
        s  += __shfl_down_sync(0xffffffffu, s,  o);
        sq += __shfl_down_sync(0xffffffffu, sq, o);
    }
    __shared__ float ssh[8], sqsh[8];
    __shared__ float s_mu, s_rs;
    if ((tid & 31) == 0) { ssh[tid >> 5] = s; sqsh[tid >> 5] = sq; }
    __syncthreads();
    if (tid == 0) {
        float S = 0.f, Q = 0.f;
        #pragma unroll
        for (int w = 0; w < 8; w++) { S += ssh[w]; Q += sqsh[w]; }
        const float mu  = S * (1.f / Ec);
        const float var = Q * (1.f / Ec) - mu * mu;
        s_mu = mu;
        s_rs = rsqrtf(var + 1e-6f);
    }
    __syncthreads();
    const float mu = s_mu, rs = s_rs;
    const float4 g  = *(const float4*)(gamma + tid * 4);
    const float4 be = *(const float4*)(beta + tid * 4);
    float4 o4;
    o4.x = g.x * (v.x - mu) * rs + be.x;
    o4.y = g.y * (v.y - mu) * rs + be.y;
    o4.z = g.z * (v.z - mu) * rs + be.z;
    o4.w = g.w * (v.w - mu) * rs + be.w;
    *(float4*)(out + (size_t)row * Ec + tid * 4) = o4;
}

// ---------------- launch ----------------
extern "C" void kernel_launch(void* const* d_in, const int* in_sizes, int n_in,
                              void* d_out, int out_size)
{
    const float* x     = (const float*)d_in[0];
    const float* q_w   = (const float*)d_in[1];
    const float* q_b   = (const float*)d_in[2];
    const float* k_w   = (const float*)d_in[3];
    const float* k_b   = (const float*)d_in[4];
    const float* v_w   = (const float*)d_in[5];
    const float* v_b   = (const float*)d_in[6];
    const float* out_w = (const float*)d_in[7];
    const float* out_b = (const float*)d_in[8];
    const float* proj  = (const float*)d_in[9];
    const float* gamma = (const float*)d_in[10];
    const float* beta  = (const float*)d_in[11];
    float* out = (float*)d_out;

    float *Qp, *Kp, *Vp, *qpp, *kpp, *attnp, *resp;
    __nv_bfloat16 *xh, *xl, *ah, *al, *wth, *wtl;
    cudaGetSymbolAddress((void**)&Qp,    g_Q);
    cudaGetSymbolAddress((void**)&Kp,    g_K);
    cudaGetSymbolAddress((void**)&Vp,    g_V);
    cudaGetSymbolAddress((void**)&qpp,   g_qp);
    cudaGetSymbolAddress((void**)&kpp,   g_kp);
    cudaGetSymbolAddress((void**)&attnp, g_attn);
    cudaGetSymbolAddress((void**)&resp,  g_res);
    cudaGetSymbolAddress((void**)&xh,    g_xh);
    cudaGetSymbolAddress((void**)&xl,    g_xl);
    cudaGetSymbolAddress((void**)&ah,    g_ah);
    cudaGetSymbolAddress((void**)&al,    g_al);
    cudaGetSymbolAddress((void**)&wth,   g_wth);
    cudaGetSymbolAddress((void**)&wtl,   g_wtl);

    cudaFuncSetAttribute(bgemm_mma, cudaFuncAttributeMaxDynamicSharedMemorySize, 98304);

    const int NE = Bc * Sc * Ec;                 // 8388608
    const dim3 gw(32, 32);
    const dim3 gb(Ec / 128, (Bc * Sc) / 128);    // (8, 64)
    const dim3 gf(Mc / 128, (Bc * Sc * Hc) / 128);

    split_kernel<<<NE / 1024, 256>>>(x, xh, xl);
    wsplit_t<<<gw, 256>>>(q_w,   wth + 0 * Ec * Ec, wtl + 0 * Ec * Ec);
    wsplit_t<<<gw, 256>>>(k_w,   wth + 1 * Ec * Ec, wtl + 1 * Ec * Ec);
    wsplit_t<<<gw, 256>>>(v_w,   wth + 2 * Ec * Ec, wtl + 2 * Ec * Ec);
    wsplit_t<<<gw, 256>>>(out_w, wth + 3 * Ec * Ec, wtl + 3 * Ec * Ec);

    bgemm_mma<<<gb, 256, 98304>>>(xh, xl, wth + 0 * Ec * Ec, wtl + 0 * Ec * Ec, q_b, nullptr, Qp);
    bgemm_mma<<<gb, 256, 98304>>>(xh, xl, wth + 1 * Ec * Ec, wtl + 1 * Ec * Ec, k_b, nullptr, Kp);
    bgemm_mma<<<gb, 256, 98304>>>(xh, xl, wth + 2 * Ec * Ec, wtl + 2 * Ec * Ec, v_b, nullptr, Vp);

    feature_kernel<<<gf, 256>>>(Qp, proj, qpp);
    feature_kernel<<<gf, 256>>>(Kp, proj, kpp);

    scan_kernel<<<Bc * Hc, 256>>>(qpp, kpp, Vp, attnp);

    split_kernel<<<NE / 1024, 256>>>(attnp, ah, al);
    bgemm_mma<<<gb, 256, 98304>>>(ah, al, wth + 3 * Ec * Ec, wtl + 3 * Ec * Ec, out_b, x, resp);

    ln_kernel<<<Bc * Sc, 256>>>(resp, gamma, beta, out);
}